// round 11
// baseline (speedup 1.0000x reference)
#include <cuda_runtime.h>
#include <math.h>

#define N_NODES 50000
#define N_EDGES 25000
#define NNZ     600000
#define D       128
#define H       256

// ---------------- scratch (device globals; no allocation allowed) ----------
__device__ float g_h1[N_NODES * D];
__device__ float g_h2[N_NODES * D];
__device__ float g_m1[N_NODES * H];
__device__ float g_m2[N_NODES * D];
__device__ float g_eacc[N_EDGES * D];
__device__ float g_nacc[N_NODES * D];

__device__ int g_ecnt[N_EDGES];
__device__ int g_vcnt[N_NODES];
__device__ int g_eoff[N_EDGES + 1];
__device__ int g_voff[N_NODES + 1];
__device__ int g_ecur[N_EDGES];
__device__ int g_vcur[N_NODES];
__device__ int g_ev[NNZ];   // vertex ids grouped by edge
__device__ int g_ve[NNZ];   // edge ids grouped by vertex

// ---------------- CSR build -------------------------------------------------
__global__ void count_kernel(const int* __restrict__ v_idx,
                             const int* __restrict__ e_idx,
                             int* __restrict__ ecnt,
                             int* __restrict__ vcnt) {
    int k = blockIdx.x * blockDim.x + threadIdx.x;
    if (k < NNZ) {
        atomicAdd(&ecnt[e_idx[k]], 1);
        atomicAdd(&vcnt[v_idx[k]], 1);
    }
}

// single-block exclusive scan (warp-shuffle based), n up to ~50k
__global__ void scan_excl(const int* __restrict__ cnt, int* __restrict__ off, int n) {
    __shared__ int wsum[32];
    __shared__ int carry_s;
    int lane = threadIdx.x & 31;
    int wid = threadIdx.x >> 5;
    if (threadIdx.x == 0) carry_s = 0;
    __syncthreads();
    for (int base = 0; base < n; base += 1024) {
        int i = base + threadIdx.x;
        int v = (i < n) ? cnt[i] : 0;
        int x = v;
#pragma unroll
        for (int d = 1; d < 32; d <<= 1) {
            int t = __shfl_up_sync(0xFFFFFFFFu, x, d);
            if (lane >= d) x += t;
        }
        if (lane == 31) wsum[wid] = x;
        __syncthreads();
        if (wid == 0) {
            int w = wsum[lane];
            int y = w;
#pragma unroll
            for (int d = 1; d < 32; d <<= 1) {
                int t = __shfl_up_sync(0xFFFFFFFFu, y, d);
                if (lane >= d) y += t;
            }
            wsum[lane] = y - w;  // exclusive warp offset
        }
        __syncthreads();
        int excl = carry_s + wsum[wid] + x - v;
        if (i < n) off[i] = excl;
        __syncthreads();
        if (threadIdx.x == 1023) carry_s = excl + v;
        __syncthreads();
    }
    if (threadIdx.x == 0) off[n] = carry_s;
}

__global__ void fill_csr(const int* __restrict__ v_idx,
                         const int* __restrict__ e_idx,
                         const int* __restrict__ eoff,
                         const int* __restrict__ voff,
                         int* __restrict__ ecur, int* __restrict__ vcur,
                         int* __restrict__ ev, int* __restrict__ ve) {
    int k = blockIdx.x * blockDim.x + threadIdx.x;
    if (k >= NNZ) return;
    int v = v_idx[k];
    int e = e_idx[k];
    int p = atomicAdd(&ecur[e], 1);
    ev[eoff[e] + p] = v;
    int q = atomicAdd(&vcur[v], 1);
    ve[voff[v] + q] = e;
}

// ---------------- gather aggregation (atomic-free) --------------------------
// efeat[e] = mean over vertices v in edge e of m[v]
__global__ void gather_v2e(const float* __restrict__ m,
                           const int* __restrict__ eoff,
                           const int* __restrict__ ev,
                           float* __restrict__ efeat) {
    int w = (blockIdx.x * blockDim.x + threadIdx.x) >> 5;
    int lane = threadIdx.x & 31;
    if (w >= N_EDGES) return;
    int s = eoff[w], t = eoff[w + 1];
    float4 acc = make_float4(0.f, 0.f, 0.f, 0.f);
    for (int j = s; j < t; j++) {
        int v = __ldg(&ev[j]);
        float4 r = __ldg((const float4*)&m[(size_t)v * D] + lane);
        acc.x += r.x; acc.y += r.y; acc.z += r.z; acc.w += r.w;
    }
    float inv = 1.0f / fmaxf((float)(t - s), 1.0f);
    acc.x *= inv; acc.y *= inv; acc.z *= inv; acc.w *= inv;
    ((float4*)&efeat[(size_t)w * D])[lane] = acc;
}

// nacc[v] = mean over edges e incident to v of efeat[e]
__global__ void gather_e2v(const float* __restrict__ efeat,
                           const int* __restrict__ voff,
                           const int* __restrict__ ve,
                           float* __restrict__ nacc) {
    int w = (blockIdx.x * blockDim.x + threadIdx.x) >> 5;
    int lane = threadIdx.x & 31;
    if (w >= N_NODES) return;
    int s = voff[w], t = voff[w + 1];
    float4 acc = make_float4(0.f, 0.f, 0.f, 0.f);
    for (int j = s; j < t; j++) {
        int e = __ldg(&ve[j]);
        float4 r = __ldg((const float4*)&efeat[(size_t)e * D] + lane);
        acc.x += r.x; acc.y += r.y; acc.z += r.z; acc.w += r.w;
    }
    float inv = 1.0f / fmaxf((float)(t - s), 1.0f);
    acc.x *= inv; acc.y *= inv; acc.z *= inv; acc.w *= inv;
    ((float4*)&nacc[(size_t)w * D])[lane] = acc;
}

// ---------------- SGEMM 128x128x8, 8x8 microtile ----------------------------
// C = relu(A @ B^T + bias (+ addmat)),  A:[M,K] B:[N,K] row-major
#define GBM 128
#define GBN 128
#define GBK 8

__global__ __launch_bounds__(256)
void gemm128(const float* __restrict__ A,
             const float* __restrict__ B,
             const float* __restrict__ bias,
             const float* __restrict__ addmat,
             float* __restrict__ C,
             int M, int N, int K, int do_relu) {
    __shared__ float As[GBK][GBM + 4];
    __shared__ float Bs[GBK][GBN + 4];

    int bm = blockIdx.y * GBM;
    int bn = blockIdx.x * GBN;
    int tid = threadIdx.x;
    int tx = tid % 16;
    int ty = tid / 16;

    int lrow = tid >> 1;          // 0..127
    int lcol = (tid & 1) * 4;     // 0 or 4

    float acc[8][8];
#pragma unroll
    for (int i = 0; i < 8; i++)
#pragma unroll
        for (int j = 0; j < 8; j++) acc[i][j] = 0.0f;

    for (int k0 = 0; k0 < K; k0 += GBK) {
        float4 av;
        int gr = bm + lrow;
        if (gr < M) av = *(const float4*)&A[(size_t)gr * K + k0 + lcol];
        else        av = make_float4(0.f, 0.f, 0.f, 0.f);
        As[lcol + 0][lrow] = av.x;
        As[lcol + 1][lrow] = av.y;
        As[lcol + 2][lrow] = av.z;
        As[lcol + 3][lrow] = av.w;

        float4 bv = *(const float4*)&B[(size_t)(bn + lrow) * K + k0 + lcol];
        Bs[lcol + 0][lrow] = bv.x;
        Bs[lcol + 1][lrow] = bv.y;
        Bs[lcol + 2][lrow] = bv.z;
        Bs[lcol + 3][lrow] = bv.w;
        __syncthreads();

#pragma unroll
        for (int k = 0; k < GBK; k++) {
            float a[8], b[8];
            *(float4*)&a[0] = *(const float4*)&As[k][ty * 8];
            *(float4*)&a[4] = *(const float4*)&As[k][ty * 8 + 4];
            *(float4*)&b[0] = *(const float4*)&Bs[k][tx * 8];
            *(float4*)&b[4] = *(const float4*)&Bs[k][tx * 8 + 4];
#pragma unroll
            for (int i = 0; i < 8; i++)
#pragma unroll
                for (int j = 0; j < 8; j++) acc[i][j] += a[i] * b[j];
        }
        __syncthreads();
    }

#pragma unroll
    for (int i = 0; i < 8; i++) {
        int r = bm + ty * 8 + i;
        if (r >= M) continue;
#pragma unroll
        for (int j = 0; j < 8; j++) {
            int c = bn + tx * 8 + j;
            float v = acc[i][j] + bias[c];
            if (addmat) v += addmat[(size_t)r * N + c];
            if (do_relu) v = fmaxf(v, 0.0f);
            C[(size_t)r * N + c] = v;
        }
    }
}

// ---------------- head: logits + log_softmax (warp per node) ---------------
__global__ void head_kernel(const float* __restrict__ h,
                            const float* __restrict__ Wa,
                            const float* __restrict__ ba,
                            float* __restrict__ out) {
    int gwarp = (blockIdx.x * blockDim.x + threadIdx.x) / 32;
    int lane = threadIdx.x % 32;
    if (gwarp >= N_NODES) return;
    const float* hr = h + (size_t)gwarp * D;
    float acc[4] = {0.f, 0.f, 0.f, 0.f};
#pragma unroll
    for (int t = 0; t < 4; t++) {
        float hv = __ldg(&hr[t * 32 + lane]);
#pragma unroll
        for (int c = 0; c < 4; c++)
            acc[c] += hv * __ldg(&Wa[c * D + t * 32 + lane]);
    }
#pragma unroll
    for (int off = 16; off > 0; off >>= 1)
#pragma unroll
        for (int c = 0; c < 4; c++)
            acc[c] += __shfl_xor_sync(0xFFFFFFFFu, acc[c], off);
    if (lane == 0) {
        float a[4];
#pragma unroll
        for (int c = 0; c < 4; c++) a[c] = acc[c] + ba[c];
        float mx = fmaxf(fmaxf(a[0], a[1]), fmaxf(a[2], a[3]));
        float s = 0.0f;
#pragma unroll
        for (int c = 0; c < 4; c++) s += expf(a[c] - mx);
        float ls = logf(s);
#pragma unroll
        for (int c = 0; c < 4; c++) out[(size_t)gwarp * 4 + c] = a[c] - mx - ls;
    }
}

// ---------------- host orchestration ---------------------------------------
static void run_layer(const float* hin, float* hout,
                      const float* W1, const float* b1,
                      const float* W2, const float* b2,
                      const float* Wu, const float* bu,
                      float* m1, float* m2, float* eacc, float* nacc,
                      const int* eoff, const int* ev,
                      const int* voff, const int* ve) {
    dim3 blk(256);
    // m1 = relu(h @ W1^T + b1)   [N_NODES, H], K = D
    {
        dim3 grid(H / GBN, (N_NODES + GBM - 1) / GBM);
        gemm128<<<grid, blk>>>(hin, W1, b1, nullptr, m1, N_NODES, H, D, 1);
    }
    // m2 = relu(m1 @ W2^T + b2)  [N_NODES, D], K = H
    {
        dim3 grid(D / GBN, (N_NODES + GBM - 1) / GBM);
        gemm128<<<grid, blk>>>(m1, W2, b2, nullptr, m2, N_NODES, D, H, 1);
    }
    // aggregation (gather, atomic-free; means folded in)
    gather_v2e<<<(N_EDGES * 32 + 255) / 256, 256>>>(m2, eoff, ev, eacc);
    gather_e2v<<<(N_NODES * 32 + 255) / 256, 256>>>(eacc, voff, ve, nacc);
    // hout = relu(h @ Wu^T + bu + nacc)   [N_NODES, D], K = D
    {
        dim3 grid(D / GBN, (N_NODES + GBM - 1) / GBM);
        gemm128<<<grid, blk>>>(hin, Wu, bu, nacc, hout, N_NODES, D, D, 1);
    }
}

extern "C" void kernel_launch(void* const* d_in, const int* in_sizes, int n_in,
                              void* d_out, int out_size) {
    const float* x    = (const float*)d_in[0];
    const int*   vidx = (const int*)d_in[1];
    const int*   eidx = (const int*)d_in[2];
    const float* W1   = (const float*)d_in[3];
    const float* b1   = (const float*)d_in[4];
    const float* W2   = (const float*)d_in[5];
    const float* b2   = (const float*)d_in[6];
    const float* Wu   = (const float*)d_in[7];
    const float* bu   = (const float*)d_in[8];
    const float* Wa   = (const float*)d_in[9];
    const float* ba   = (const float*)d_in[10];
    float* out = (float*)d_out;

    float *h1, *h2, *m1, *m2, *eacc, *nacc;
    int *ecnt, *vcnt, *eoff, *voff, *ecur, *vcur, *ev, *ve;
    cudaGetSymbolAddress((void**)&h1,   g_h1);
    cudaGetSymbolAddress((void**)&h2,   g_h2);
    cudaGetSymbolAddress((void**)&m1,   g_m1);
    cudaGetSymbolAddress((void**)&m2,   g_m2);
    cudaGetSymbolAddress((void**)&eacc, g_eacc);
    cudaGetSymbolAddress((void**)&nacc, g_nacc);
    cudaGetSymbolAddress((void**)&ecnt, g_ecnt);
    cudaGetSymbolAddress((void**)&vcnt, g_vcnt);
    cudaGetSymbolAddress((void**)&eoff, g_eoff);
    cudaGetSymbolAddress((void**)&voff, g_voff);
    cudaGetSymbolAddress((void**)&ecur, g_ecur);
    cudaGetSymbolAddress((void**)&vcur, g_vcur);
    cudaGetSymbolAddress((void**)&ev,   g_ev);
    cudaGetSymbolAddress((void**)&ve,   g_ve);

    // ---- CSR build (once; shared by both layers) ----
    cudaMemsetAsync(ecnt, 0, N_EDGES * sizeof(int));
    cudaMemsetAsync(vcnt, 0, N_NODES * sizeof(int));
    cudaMemsetAsync(ecur, 0, N_EDGES * sizeof(int));
    cudaMemsetAsync(vcur, 0, N_NODES * sizeof(int));
    count_kernel<<<(NNZ + 255) / 256, 256>>>(vidx, eidx, ecnt, vcnt);
    scan_excl<<<1, 1024>>>(ecnt, eoff, N_EDGES);
    scan_excl<<<1, 1024>>>(vcnt, voff, N_NODES);
    fill_csr<<<(NNZ + 255) / 256, 256>>>(vidx, eidx, eoff, voff, ecur, vcur, ev, ve);

    // ---- two hypergraph-conv layers ----
    run_layer(x,  h1, W1, b1, W2, b2, Wu, bu, m1, m2, eacc, nacc, eoff, ev, voff, ve);
    run_layer(h1, h2, W1, b1, W2, b2, Wu, bu, m1, m2, eacc, nacc, eoff, ev, voff, ve);

    // ---- head: logits + log_softmax ----
    head_kernel<<<(N_NODES * 32 + 127) / 128, 128>>>(h2, Wa, ba, out);
}

// round 12
// speedup vs baseline: 1.0039x; 1.0039x over previous
#include <cuda_runtime.h>
#include <math.h>

#define N_NODES 50000
#define N_EDGES 25000
#define NNZ     600000
#define D       128
#define H       256

// ---------------- scratch (device globals; no allocation allowed) ----------
__device__ float g_h1[N_NODES * D];
__device__ float g_h2[N_NODES * D];
__device__ float g_m1[N_NODES * H];
__device__ float g_m2[N_NODES * D];
__device__ float g_eacc[N_EDGES * D];
__device__ float g_nacc[N_NODES * D];

__device__ int g_ecnt[N_EDGES];
__device__ int g_vcnt[N_NODES];
__device__ int g_eoff[N_EDGES + 1];
__device__ int g_voff[N_NODES + 1];
__device__ int g_ecur[N_EDGES];
__device__ int g_vcur[N_NODES];
__device__ int g_ev[NNZ];   // vertex ids grouped by edge
__device__ int g_ve[NNZ];   // edge ids grouped by vertex

// ---------------- CSR build -------------------------------------------------
__global__ void count_kernel(const int* __restrict__ v_idx,
                             const int* __restrict__ e_idx,
                             int* __restrict__ ecnt,
                             int* __restrict__ vcnt) {
    int k = blockIdx.x * blockDim.x + threadIdx.x;
    if (k < NNZ) {
        atomicAdd(&ecnt[e_idx[k]], 1);
        atomicAdd(&vcnt[v_idx[k]], 1);
    }
}

// single-block exclusive scan (warp-shuffle based), n up to ~50k
__global__ void scan_excl(const int* __restrict__ cnt, int* __restrict__ off, int n) {
    __shared__ int wsum[32];
    __shared__ int carry_s;
    int lane = threadIdx.x & 31;
    int wid = threadIdx.x >> 5;
    if (threadIdx.x == 0) carry_s = 0;
    __syncthreads();
    for (int base = 0; base < n; base += 1024) {
        int i = base + threadIdx.x;
        int v = (i < n) ? cnt[i] : 0;
        int x = v;
#pragma unroll
        for (int d = 1; d < 32; d <<= 1) {
            int t = __shfl_up_sync(0xFFFFFFFFu, x, d);
            if (lane >= d) x += t;
        }
        if (lane == 31) wsum[wid] = x;
        __syncthreads();
        if (wid == 0) {
            int w = wsum[lane];
            int y = w;
#pragma unroll
            for (int d = 1; d < 32; d <<= 1) {
                int t = __shfl_up_sync(0xFFFFFFFFu, y, d);
                if (lane >= d) y += t;
            }
            wsum[lane] = y - w;  // exclusive warp offset
        }
        __syncthreads();
        int excl = carry_s + wsum[wid] + x - v;
        if (i < n) off[i] = excl;
        __syncthreads();
        if (threadIdx.x == 1023) carry_s = excl + v;
        __syncthreads();
    }
    if (threadIdx.x == 0) off[n] = carry_s;
}

__global__ void fill_csr(const int* __restrict__ v_idx,
                         const int* __restrict__ e_idx,
                         const int* __restrict__ eoff,
                         const int* __restrict__ voff,
                         int* __restrict__ ecur, int* __restrict__ vcur,
                         int* __restrict__ ev, int* __restrict__ ve) {
    int k = blockIdx.x * blockDim.x + threadIdx.x;
    if (k >= NNZ) return;
    int v = v_idx[k];
    int e = e_idx[k];
    int p = atomicAdd(&ecur[e], 1);
    ev[eoff[e] + p] = v;
    int q = atomicAdd(&vcur[v], 1);
    ve[voff[v] + q] = e;
}

// ---------------- gather aggregation (atomic-free) --------------------------
// efeat[e] = mean over vertices v in edge e of m[v]
__global__ void gather_v2e(const float* __restrict__ m,
                           const int* __restrict__ eoff,
                           const int* __restrict__ ev,
                           float* __restrict__ efeat) {
    int w = (blockIdx.x * blockDim.x + threadIdx.x) >> 5;
    int lane = threadIdx.x & 31;
    if (w >= N_EDGES) return;
    int s = eoff[w], t = eoff[w + 1];
    float4 acc = make_float4(0.f, 0.f, 0.f, 0.f);
    for (int j = s; j < t; j++) {
        int v = __ldg(&ev[j]);
        float4 r = __ldg((const float4*)&m[(size_t)v * D] + lane);
        acc.x += r.x; acc.y += r.y; acc.z += r.z; acc.w += r.w;
    }
    float inv = 1.0f / fmaxf((float)(t - s), 1.0f);
    acc.x *= inv; acc.y *= inv; acc.z *= inv; acc.w *= inv;
    ((float4*)&efeat[(size_t)w * D])[lane] = acc;
}

// nacc[v] = mean over edges e incident to v of efeat[e]
__global__ void gather_e2v(const float* __restrict__ efeat,
                           const int* __restrict__ voff,
                           const int* __restrict__ ve,
                           float* __restrict__ nacc) {
    int w = (blockIdx.x * blockDim.x + threadIdx.x) >> 5;
    int lane = threadIdx.x & 31;
    if (w >= N_NODES) return;
    int s = voff[w], t = voff[w + 1];
    float4 acc = make_float4(0.f, 0.f, 0.f, 0.f);
    for (int j = s; j < t; j++) {
        int e = __ldg(&ve[j]);
        float4 r = __ldg((const float4*)&efeat[(size_t)e * D] + lane);
        acc.x += r.x; acc.y += r.y; acc.z += r.z; acc.w += r.w;
    }
    float inv = 1.0f / fmaxf((float)(t - s), 1.0f);
    acc.x *= inv; acc.y *= inv; acc.z *= inv; acc.w *= inv;
    ((float4*)&nacc[(size_t)w * D])[lane] = acc;
}

// ---------------- SGEMM 128x128x8, 8x8 microtile ----------------------------
// C = relu(A @ B^T + bias (+ addmat)),  A:[M,K] B:[N,K] row-major
#define GBM 128
#define GBN 128
#define GBK 8

__global__ __launch_bounds__(256)
void gemm128(const float* __restrict__ A,
             const float* __restrict__ B,
             const float* __restrict__ bias,
             const float* __restrict__ addmat,
             float* __restrict__ C,
             int M, int N, int K, int do_relu) {
    __shared__ float As[GBK][GBM + 4];
    __shared__ float Bs[GBK][GBN + 4];

    int bm = blockIdx.y * GBM;
    int bn = blockIdx.x * GBN;
    int tid = threadIdx.x;
    int tx = tid % 16;
    int ty = tid / 16;

    int lrow = tid >> 1;          // 0..127
    int lcol = (tid & 1) * 4;     // 0 or 4

    float acc[8][8];
#pragma unroll
    for (int i = 0; i < 8; i++)
#pragma unroll
        for (int j = 0; j < 8; j++) acc[i][j] = 0.0f;

    for (int k0 = 0; k0 < K; k0 += GBK) {
        float4 av;
        int gr = bm + lrow;
        if (gr < M) av = *(const float4*)&A[(size_t)gr * K + k0 + lcol];
        else        av = make_float4(0.f, 0.f, 0.f, 0.f);
        As[lcol + 0][lrow] = av.x;
        As[lcol + 1][lrow] = av.y;
        As[lcol + 2][lrow] = av.z;
        As[lcol + 3][lrow] = av.w;

        float4 bv = *(const float4*)&B[(size_t)(bn + lrow) * K + k0 + lcol];
        Bs[lcol + 0][lrow] = bv.x;
        Bs[lcol + 1][lrow] = bv.y;
        Bs[lcol + 2][lrow] = bv.z;
        Bs[lcol + 3][lrow] = bv.w;
        __syncthreads();

#pragma unroll
        for (int k = 0; k < GBK; k++) {
            float a[8], b[8];
            *(float4*)&a[0] = *(const float4*)&As[k][ty * 8];
            *(float4*)&a[4] = *(const float4*)&As[k][ty * 8 + 4];
            *(float4*)&b[0] = *(const float4*)&Bs[k][tx * 8];
            *(float4*)&b[4] = *(const float4*)&Bs[k][tx * 8 + 4];
#pragma unroll
            for (int i = 0; i < 8; i++)
#pragma unroll
                for (int j = 0; j < 8; j++) acc[i][j] += a[i] * b[j];
        }
        __syncthreads();
    }

#pragma unroll
    for (int i = 0; i < 8; i++) {
        int r = bm + ty * 8 + i;
        if (r >= M) continue;
#pragma unroll
        for (int j = 0; j < 8; j++) {
            int c = bn + tx * 8 + j;
            float v = acc[i][j] + bias[c];
            if (addmat) v += addmat[(size_t)r * N + c];
            if (do_relu) v = fmaxf(v, 0.0f);
            C[(size_t)r * N + c] = v;
        }
    }
}

// ---------------- head: logits + log_softmax (warp per node) ---------------
__global__ void head_kernel(const float* __restrict__ h,
                            const float* __restrict__ Wa,
                            const float* __restrict__ ba,
                            float* __restrict__ out) {
    int gwarp = (blockIdx.x * blockDim.x + threadIdx.x) / 32;
    int lane = threadIdx.x % 32;
    if (gwarp >= N_NODES) return;
    const float* hr = h + (size_t)gwarp * D;
    float acc[4] = {0.f, 0.f, 0.f, 0.f};
#pragma unroll
    for (int t = 0; t < 4; t++) {
        float hv = __ldg(&hr[t * 32 + lane]);
#pragma unroll
        for (int c = 0; c < 4; c++)
            acc[c] += hv * __ldg(&Wa[c * D + t * 32 + lane]);
    }
#pragma unroll
    for (int off = 16; off > 0; off >>= 1)
#pragma unroll
        for (int c = 0; c < 4; c++)
            acc[c] += __shfl_xor_sync(0xFFFFFFFFu, acc[c], off);
    if (lane == 0) {
        float a[4];
#pragma unroll
        for (int c = 0; c < 4; c++) a[c] = acc[c] + ba[c];
        float mx = fmaxf(fmaxf(a[0], a[1]), fmaxf(a[2], a[3]));
        float s = 0.0f;
#pragma unroll
        for (int c = 0; c < 4; c++) s += expf(a[c] - mx);
        float ls = logf(s);
#pragma unroll
        for (int c = 0; c < 4; c++) out[(size_t)gwarp * 4 + c] = a[c] - mx - ls;
    }
}

// ---------------- host orchestration ---------------------------------------
static void run_layer(const float* hin, float* hout,
                      const float* W1, const float* b1,
                      const float* W2, const float* b2,
                      const float* Wu, const float* bu,
                      float* m1, float* m2, float* eacc, float* nacc,
                      const int* eoff, const int* ev,
                      const int* voff, const int* ve) {
    dim3 blk(256);
    // m1 = relu(h @ W1^T + b1)   [N_NODES, H], K = D
    {
        dim3 grid(H / GBN, (N_NODES + GBM - 1) / GBM);
        gemm128<<<grid, blk>>>(hin, W1, b1, nullptr, m1, N_NODES, H, D, 1);
    }
    // m2 = relu(m1 @ W2^T + b2)  [N_NODES, D], K = H
    {
        dim3 grid(D / GBN, (N_NODES + GBM - 1) / GBM);
        gemm128<<<grid, blk>>>(m1, W2, b2, nullptr, m2, N_NODES, D, H, 1);
    }
    // aggregation (gather, atomic-free; means folded in)
    gather_v2e<<<(N_EDGES * 32 + 255) / 256, 256>>>(m2, eoff, ev, eacc);
    gather_e2v<<<(N_NODES * 32 + 255) / 256, 256>>>(eacc, voff, ve, nacc);
    // hout = relu(h @ Wu^T + bu + nacc)   [N_NODES, D], K = D
    {
        dim3 grid(D / GBN, (N_NODES + GBM - 1) / GBM);
        gemm128<<<grid, blk>>>(hin, Wu, bu, nacc, hout, N_NODES, D, D, 1);
    }
}

extern "C" void kernel_launch(void* const* d_in, const int* in_sizes, int n_in,
                              void* d_out, int out_size) {
    const float* x    = (const float*)d_in[0];
    const int*   vidx = (const int*)d_in[1];
    const int*   eidx = (const int*)d_in[2];
    const float* W1   = (const float*)d_in[3];
    const float* b1   = (const float*)d_in[4];
    const float* W2   = (const float*)d_in[5];
    const float* b2   = (const float*)d_in[6];
    const float* Wu   = (const float*)d_in[7];
    const float* bu   = (const float*)d_in[8];
    const float* Wa   = (const float*)d_in[9];
    const float* ba   = (const float*)d_in[10];
    float* out = (float*)d_out;

    float *h1, *h2, *m1, *m2, *eacc, *nacc;
    int *ecnt, *vcnt, *eoff, *voff, *ecur, *vcur, *ev, *ve;
    cudaGetSymbolAddress((void**)&h1,   g_h1);
    cudaGetSymbolAddress((void**)&h2,   g_h2);
    cudaGetSymbolAddress((void**)&m1,   g_m1);
    cudaGetSymbolAddress((void**)&m2,   g_m2);
    cudaGetSymbolAddress((void**)&eacc, g_eacc);
    cudaGetSymbolAddress((void**)&nacc, g_nacc);
    cudaGetSymbolAddress((void**)&ecnt, g_ecnt);
    cudaGetSymbolAddress((void**)&vcnt, g_vcnt);
    cudaGetSymbolAddress((void**)&eoff, g_eoff);
    cudaGetSymbolAddress((void**)&voff, g_voff);
    cudaGetSymbolAddress((void**)&ecur, g_ecur);
    cudaGetSymbolAddress((void**)&vcur, g_vcur);
    cudaGetSymbolAddress((void**)&ev,   g_ev);
    cudaGetSymbolAddress((void**)&ve,   g_ve);

    // ---- CSR build (once; shared by both layers) ----
    cudaMemsetAsync(ecnt, 0, N_EDGES * sizeof(int));
    cudaMemsetAsync(vcnt, 0, N_NODES * sizeof(int));
    cudaMemsetAsync(ecur, 0, N_EDGES * sizeof(int));
    cudaMemsetAsync(vcur, 0, N_NODES * sizeof(int));
    count_kernel<<<(NNZ + 255) / 256, 256>>>(vidx, eidx, ecnt, vcnt);
    scan_excl<<<1, 1024>>>(ecnt, eoff, N_EDGES);
    scan_excl<<<1, 1024>>>(vcnt, voff, N_NODES);
    fill_csr<<<(NNZ + 255) / 256, 256>>>(vidx, eidx, eoff, voff, ecur, vcur, ev, ve);

    // ---- two hypergraph-conv layers ----
    run_layer(x,  h1, W1, b1, W2, b2, Wu, bu, m1, m2, eacc, nacc, eoff, ev, voff, ve);
    run_layer(h1, h2, W1, b1, W2, b2, Wu, bu, m1, m2, eacc, nacc, eoff, ev, voff, ve);

    // ---- head: logits + log_softmax ----
    head_kernel<<<(N_NODES * 32 + 127) / 128, 128>>>(h2, Wa, ba, out);
}